// round 1
// baseline (speedup 1.0000x reference)
#include <cuda_runtime.h>
#include <math.h>

// PA-MPJPE: per batch element, Procrustes-align pred to gt (rotation+scale+
// translation), then mean per-joint L2 error.
//
// Key identities used (see analysis):
//  - pelvis alignment is a no-op (cancels under optimal translation)
//  - loss_j = || scale * R * (p_j - mu_p)  -  (g_j - mu_g) ||
//  - R = argmax_{SO(3)} trace(R K), K = sum (p-mu_p)(g-mu_g)^T
//    obtained via Horn's quaternion method (max eigvec of symmetric 4x4 N)
//  - scale = trace(R K) / var1, var1 = sum |p - mu_p|^2

constexpr int J      = 14;
constexpr int FPE    = J * 3;   // 42 floats per element
constexpr int TPB    = 128;
constexpr int STRIDE = 43;      // 43 mod 32 = 11, coprime with 32 -> conflict-free LDS

template<int P, int Q>
__device__ __forceinline__ void jacobi_rot(float (&A)[4][4], float (&V)[4][4]) {
    float apq = A[P][Q];
    if (fabsf(apq) < 1e-20f) return;
    float theta = 0.5f * (A[Q][Q] - A[P][P]) / apq;
    float t = 1.0f / (fabsf(theta) + sqrtf(theta * theta + 1.0f));
    t = (theta >= 0.0f) ? t : -t;
    float c = rsqrtf(t * t + 1.0f);
    float s = t * c;
    #pragma unroll
    for (int k = 0; k < 4; k++) {
        float akp = A[k][P], akq = A[k][Q];
        A[k][P] = c * akp - s * akq;
        A[k][Q] = s * akp + c * akq;
    }
    #pragma unroll
    for (int k = 0; k < 4; k++) {
        float apk = A[P][k], aqk = A[Q][k];
        A[P][k] = c * apk - s * aqk;
        A[Q][k] = s * apk + c * aqk;
    }
    #pragma unroll
    for (int k = 0; k < 4; k++) {
        float vkp = V[k][P], vkq = V[k][Q];
        V[k][P] = c * vkp - s * vkq;
        V[k][Q] = s * vkp + c * vkq;
    }
}

__global__ void __launch_bounds__(TPB, 4)
pampjpe_kernel(const float* __restrict__ pred,
               const float* __restrict__ gt,
               float* __restrict__ out, int B)
{
    __shared__ float sp[TPB * STRIDE];
    __shared__ float sg[TPB * STRIDE];
    const int tid = threadIdx.x;
    const long long base  = (long long)blockIdx.x * (TPB * FPE);
    const long long total = (long long)B * FPE;

    // Coalesced global -> shared staging (per-element rows, padded stride)
    #pragma unroll
    for (int k = 0; k < FPE; k++) {
        int idx = tid + k * TPB;
        long long gidx = base + idx;
        float vp = 0.0f, vg = 0.0f;
        if (gidx < total) { vp = pred[gidx]; vg = gt[gidx]; }
        int e = idx / FPE;
        int r = idx - e * FPE;
        sp[e * STRIDE + r] = vp;
        sg[e * STRIDE + r] = vg;
    }
    __syncthreads();

    const int elem = blockIdx.x * TPB + tid;
    if (elem >= B) return;

    const float* p = sp + tid * STRIDE;
    const float* g = sg + tid * STRIDE;

    // ---- pass 1: raw sums and cross products ----
    float sax = 0.f, say = 0.f, saz = 0.f;
    float sbx = 0.f, sby = 0.f, sbz = 0.f;
    float saa = 0.f;
    float S00 = 0.f, S01 = 0.f, S02 = 0.f;
    float S10 = 0.f, S11 = 0.f, S12 = 0.f;
    float S20 = 0.f, S21 = 0.f, S22 = 0.f;
    #pragma unroll
    for (int j = 0; j < J; j++) {
        float ax = p[3*j+0], ay = p[3*j+1], az = p[3*j+2];
        float bx = g[3*j+0], by = g[3*j+1], bz = g[3*j+2];
        sax += ax; say += ay; saz += az;
        sbx += bx; sby += by; sbz += bz;
        saa += ax*ax + ay*ay + az*az;
        S00 += ax*bx; S01 += ax*by; S02 += ax*bz;
        S10 += ay*bx; S11 += ay*by; S12 += ay*bz;
        S20 += az*bx; S21 += az*by; S22 += az*bz;
    }
    const float invJ = 1.0f / (float)J;
    const float max_ = sax*invJ, may_ = say*invJ, maz_ = saz*invJ;
    const float mbx  = sbx*invJ, mby  = sby*invJ, mbz  = sbz*invJ;

    // centered covariance K = S - sa * mb^T ;  var1 = saa - sa . ma
    const float K00 = S00 - sax*mbx, K01 = S01 - sax*mby, K02 = S02 - sax*mbz;
    const float K10 = S10 - say*mbx, K11 = S11 - say*mby, K12 = S12 - say*mbz;
    const float K20 = S20 - saz*mbx, K21 = S21 - saz*mby, K22 = S22 - saz*mbz;
    const float var1 = saa - (sax*max_ + say*may_ + saz*maz_);

    // ---- Horn's symmetric 4x4 ----
    float A[4][4];
    A[0][0] =  K00 + K11 + K22;
    A[0][1] =  K12 - K21;   A[1][0] = A[0][1];
    A[0][2] =  K20 - K02;   A[2][0] = A[0][2];
    A[0][3] =  K01 - K10;   A[3][0] = A[0][3];
    A[1][1] =  K00 - K11 - K22;
    A[1][2] =  K01 + K10;   A[2][1] = A[1][2];
    A[1][3] =  K20 + K02;   A[3][1] = A[1][3];
    A[2][2] = -K00 + K11 - K22;
    A[2][3] =  K12 + K21;   A[3][2] = A[2][3];
    A[3][3] = -K00 - K11 + K22;

    float V[4][4] = {{1.f,0.f,0.f,0.f},
                     {0.f,1.f,0.f,0.f},
                     {0.f,0.f,1.f,0.f},
                     {0.f,0.f,0.f,1.f}};

    #pragma unroll
    for (int sweep = 0; sweep < 5; sweep++) {
        jacobi_rot<0,1>(A, V);
        jacobi_rot<0,2>(A, V);
        jacobi_rot<0,3>(A, V);
        jacobi_rot<1,2>(A, V);
        jacobi_rot<1,3>(A, V);
        jacobi_rot<2,3>(A, V);
    }

    // max-eigenvalue eigenvector = quaternion (w,x,y,z)
    float best = A[0][0];
    float qw = V[0][0], qx = V[1][0], qy = V[2][0], qz = V[3][0];
    if (A[1][1] > best) { best = A[1][1]; qw = V[0][1]; qx = V[1][1]; qy = V[2][1]; qz = V[3][1]; }
    if (A[2][2] > best) { best = A[2][2]; qw = V[0][2]; qx = V[1][2]; qy = V[2][2]; qz = V[3][2]; }
    if (A[3][3] > best) { best = A[3][3]; qw = V[0][3]; qx = V[1][3]; qy = V[2][3]; qz = V[3][3]; }

    float rn = rsqrtf(qw*qw + qx*qx + qy*qy + qz*qz);
    qw *= rn; qx *= rn; qy *= rn; qz *= rn;

    // quaternion -> rotation matrix (maps pred-frame to gt-frame)
    const float xx = qx*qx, yy = qy*qy, zz = qz*qz;
    const float xy = qx*qy, xz = qx*qz, yz = qy*qz;
    const float wx = qw*qx, wy = qw*qy, wz = qw*qz;
    const float R00 = 1.f - 2.f*(yy + zz), R01 = 2.f*(xy - wz),       R02 = 2.f*(xz + wy);
    const float R10 = 2.f*(xy + wz),       R11 = 1.f - 2.f*(xx + zz), R12 = 2.f*(yz - wx);
    const float R20 = 2.f*(xz - wy),       R21 = 2.f*(yz + wx),       R22 = 1.f - 2.f*(xx + yy);

    // trace(R K) = sum_ij R[i][j] * K[j][i]
    const float trRK = R00*K00 + R01*K10 + R02*K20
                     + R10*K01 + R11*K11 + R12*K21
                     + R20*K02 + R21*K12 + R22*K22;
    const float scale = trRK / var1;

    // ---- pass 2: loss = mean_j || scale*R*(p_j-mu_p) - (g_j-mu_g) || ----
    float acc = 0.f;
    #pragma unroll
    for (int j = 0; j < J; j++) {
        float ax = p[3*j+0] - max_, ay = p[3*j+1] - may_, az = p[3*j+2] - maz_;
        float bx = g[3*j+0] - mbx,  by = g[3*j+1] - mby,  bz = g[3*j+2] - mbz;
        float ex = scale * (R00*ax + R01*ay + R02*az) - bx;
        float ey = scale * (R10*ax + R11*ay + R12*az) - by;
        float ez = scale * (R20*ax + R21*ay + R22*az) - bz;
        acc += sqrtf(ex*ex + ey*ey + ez*ez);
    }
    out[elem] = acc * invJ;
}

extern "C" void kernel_launch(void* const* d_in, const int* in_sizes, int n_in,
                              void* d_out, int out_size)
{
    const float* pred = (const float*)d_in[0];
    const float* gt   = (const float*)d_in[1];
    float* out = (float*)d_out;
    const int B = out_size;                 // output is (B,)
    const int blocks = (B + TPB - 1) / TPB;
    pampjpe_kernel<<<blocks, TPB>>>(pred, gt, out, B);
}

// round 3
// speedup vs baseline: 1.3336x; 1.3336x over previous
#include <cuda_runtime.h>
#include <math.h>

// PA-MPJPE via Horn quaternion + QUEST-style Newton eigenvalue + adjugate
// eigenvector. Pelvis alignment provably cancels (optimal translation).

constexpr int J   = 14;
constexpr int FPE = J * 3;         // 42 floats per element
constexpr int TPB = 128;
constexpr int TILE_F  = TPB * FPE; // 5376 floats per block per array
constexpr int TILE_V4 = TILE_F / 4; // 1344 float4

__device__ __forceinline__ float det3(float a, float b, float c,
                                      float d, float e, float f,
                                      float g, float h, float i) {
    return a * (e * i - f * h) - b * (d * i - f * g) + c * (d * h - e * g);
}

__global__ void __launch_bounds__(TPB, 5)
pampjpe_kernel(const float* __restrict__ pred,
               const float* __restrict__ gt,
               float* __restrict__ out, int B)
{
    __shared__ float sp[TILE_F];
    __shared__ float sg[TILE_F];
    const int tid = threadIdx.x;
    const long long base  = (long long)blockIdx.x * TILE_F;
    const long long total = (long long)B * FPE;

    // ---- staging: global -> shared, vectorized fast path ----
    if (base + TILE_F <= total) {
        const float4* pin = reinterpret_cast<const float4*>(pred + base);
        const float4* gin = reinterpret_cast<const float4*>(gt   + base);
        float4* sp4 = reinterpret_cast<float4*>(sp);
        float4* sg4 = reinterpret_cast<float4*>(sg);
        #pragma unroll
        for (int k = 0; k < 11; k++) {
            int idx4 = tid + k * TPB;
            if (k < 10 || idx4 < TILE_V4) {
                sp4[idx4] = pin[idx4];
                sg4[idx4] = gin[idx4];
            }
        }
    } else {
        int rem = (int)(total - base);
        for (int idx = tid; idx < rem; idx += TPB) {
            sp[idx] = pred[base + idx];
            sg[idx] = gt[base + idx];
        }
    }
    __syncthreads();

    const int elem = blockIdx.x * TPB + tid;
    if (elem >= B) return;

    const float2* P2 = reinterpret_cast<const float2*>(sp + tid * FPE);
    const float2* G2 = reinterpret_cast<const float2*>(sg + tid * FPE);

    // ---- pass 1: sums, |a|^2, cross-covariance S = sum a b^T ----
    float sax = 0.f, say = 0.f, saz = 0.f;
    float sbx = 0.f, sby = 0.f, sbz = 0.f;
    float saa = 0.f;
    float S00 = 0.f, S01 = 0.f, S02 = 0.f;
    float S10 = 0.f, S11 = 0.f, S12 = 0.f;
    float S20 = 0.f, S21 = 0.f, S22 = 0.f;
    #pragma unroll
    for (int c = 0; c < 7; c++) {
        float2 a0 = P2[3*c], a1 = P2[3*c+1], a2 = P2[3*c+2];
        float2 b0 = G2[3*c], b1 = G2[3*c+1], b2 = G2[3*c+2];
        // joint 2c
        {
            float ax = a0.x, ay = a0.y, az = a1.x;
            float bx = b0.x, by = b0.y, bz = b1.x;
            sax += ax; say += ay; saz += az;
            sbx += bx; sby += by; sbz += bz;
            saa += ax*ax + ay*ay + az*az;
            S00 += ax*bx; S01 += ax*by; S02 += ax*bz;
            S10 += ay*bx; S11 += ay*by; S12 += ay*bz;
            S20 += az*bx; S21 += az*by; S22 += az*bz;
        }
        // joint 2c+1
        {
            float ax = a1.y, ay = a2.x, az = a2.y;
            float bx = b1.y, by = b2.x, bz = b2.y;
            sax += ax; say += ay; saz += az;
            sbx += bx; sby += by; sbz += bz;
            saa += ax*ax + ay*ay + az*az;
            S00 += ax*bx; S01 += ax*by; S02 += ax*bz;
            S10 += ay*bx; S11 += ay*by; S12 += ay*bz;
            S20 += az*bx; S21 += az*by; S22 += az*bz;
        }
    }
    const float invJ = 1.0f / (float)J;
    const float max_ = sax*invJ, may_ = say*invJ, maz_ = saz*invJ;
    const float mbx  = sbx*invJ, mby  = sby*invJ, mbz  = sbz*invJ;

    // centered covariance K and var1
    const float K00 = S00 - sax*mbx, K01 = S01 - sax*mby, K02 = S02 - sax*mbz;
    const float K10 = S10 - say*mbx, K11 = S11 - say*mby, K12 = S12 - say*mbz;
    const float K20 = S20 - saz*mbx, K21 = S21 - saz*mby, K22 = S22 - saz*mbz;
    const float var1 = saa - (sax*max_ + say*may_ + saz*maz_);

    // ---- Horn's symmetric traceless 4x4 N (10 unique entries) ----
    const float n00 =  K00 + K11 + K22;
    const float n01 =  K12 - K21;
    const float n02 =  K20 - K02;
    const float n03 =  K01 - K10;
    const float n11 =  K00 - K11 - K22;
    const float n12 =  K01 + K10;
    const float n13 =  K20 + K02;
    const float n22 = -K00 + K11 - K22;
    const float n23 =  K12 + K21;
    const float n33 = -K00 - K11 + K22;

    // ---- characteristic quartic via power traces (trace N = 0) ----
    // T = N^2 (symmetric)
    const float t00 = n00*n00 + n01*n01 + n02*n02 + n03*n03;
    const float t01 = n00*n01 + n01*n11 + n02*n12 + n03*n13;
    const float t02 = n00*n02 + n01*n12 + n02*n22 + n03*n23;
    const float t03 = n00*n03 + n01*n13 + n02*n23 + n03*n33;
    const float t11 = n01*n01 + n11*n11 + n12*n12 + n13*n13;
    const float t12 = n01*n02 + n11*n12 + n12*n22 + n13*n23;
    const float t13 = n01*n03 + n11*n13 + n12*n23 + n13*n33;
    const float t22 = n02*n02 + n12*n12 + n22*n22 + n23*n23;
    const float t23 = n02*n03 + n12*n13 + n22*n23 + n23*n33;
    const float t33 = n03*n03 + n13*n13 + n23*n23 + n33*n33;

    const float p2 = t00 + t11 + t22 + t33;                       // tr(N^2)
    const float p3 = n00*t00 + n11*t11 + n22*t22 + n33*t33
                   + 2.f*(n01*t01 + n02*t02 + n03*t03
                        + n12*t12 + n13*t13 + n23*t23);           // tr(N^3)
    const float p4 = t00*t00 + t11*t11 + t22*t22 + t33*t33
                   + 2.f*(t01*t01 + t02*t02 + t03*t03
                        + t12*t12 + t13*t13 + t23*t23);           // tr(N^4)

    // char poly: l^4 + c2 l^2 + c1 l + c0
    const float c2 = -0.5f * p2;
    const float c1 = -(1.0f/3.0f) * p3;
    const float c0 = 0.125f * p2 * p2 - 0.25f * p4;

    // Newton from upper bound sqrt(3/4 * p2) >= lambda_max (monotone)
    float lam = sqrtf(0.75f * p2);
    #pragma unroll
    for (int it = 0; it < 9; it++) {
        float lam2 = lam * lam;
        float f  = ((lam2 + c2) * lam + c1) * lam + c0;
        float fp = (4.f * lam2 + 2.f * c2) * lam + c1;
        lam -= f / fmaxf(fp, 1e-20f);
    }

    // ---- eigenvector = column of adj(N - lam I) (pick best-conditioned) ----
    const float m00 = n00 - lam, m11 = n11 - lam;
    const float m22 = n22 - lam, m33 = n33 - lam;

    const float a00 =  det3(m11, n12, n13,  n12, m22, n23,  n13, n23, m33);
    const float a01 = -det3(n01, n12, n13,  n02, m22, n23,  n03, n23, m33);
    const float a02 =  det3(n01, m11, n13,  n02, n12, n23,  n03, n13, m33);
    const float a03 = -det3(n01, m11, n12,  n02, n12, m22,  n03, n13, n23);
    const float a11 =  det3(m00, n02, n03,  n02, m22, n23,  n03, n23, m33);
    const float a12 = -det3(m00, n01, n03,  n02, n12, n23,  n03, n13, m33);
    const float a13 =  det3(m00, n01, n02,  n02, n12, m22,  n03, n13, n23);
    const float a22 =  det3(m00, n01, n03,  n01, m11, n13,  n03, n13, m33);
    const float a23 = -det3(m00, n01, n02,  n01, m11, n12,  n03, n13, n23);
    const float a33 =  det3(m00, n01, n02,  n01, m11, n12,  n02, n12, m22);

    float best = fabsf(a00);
    float qw = a00, qx = a01, qy = a02, qz = a03;
    if (fabsf(a11) > best) { best = fabsf(a11); qw = a01; qx = a11; qy = a12; qz = a13; }
    if (fabsf(a22) > best) { best = fabsf(a22); qw = a02; qx = a12; qy = a22; qz = a23; }
    if (fabsf(a33) > best) { best = fabsf(a33); qw = a03; qx = a13; qy = a23; qz = a33; }

    const float rn = rsqrtf(qw*qw + qx*qx + qy*qy + qz*qz);
    qw *= rn; qx *= rn; qy *= rn; qz *= rn;

    // quaternion -> rotation
    const float xx = qx*qx, yy = qy*qy, zz = qz*qz;
    const float xy = qx*qy, xz = qx*qz, yz = qy*qz;
    const float wx = qw*qx, wy = qw*qy, wz = qw*qz;
    const float R00 = 1.f - 2.f*(yy + zz), R01 = 2.f*(xy - wz),       R02 = 2.f*(xz + wy);
    const float R10 = 2.f*(xy + wz),       R11 = 1.f - 2.f*(xx + zz), R12 = 2.f*(yz - wx);
    const float R20 = 2.f*(xz - wy),       R21 = 2.f*(yz + wx),       R22 = 1.f - 2.f*(xx + yy);

    // scale = trace(R K)/var1 (explicit, robust to Newton residual)
    const float trRK = R00*K00 + R01*K10 + R02*K20
                     + R10*K01 + R11*K11 + R12*K21
                     + R20*K02 + R21*K12 + R22*K22;
    const float scale = trRK / var1;

    // ---- pass 2: loss = mean_j || scale*R*(a_j - mu_a) - (b_j - mu_b) || ----
    float acc = 0.f;
    #pragma unroll
    for (int c = 0; c < 7; c++) {
        float2 a0 = P2[3*c], a1 = P2[3*c+1], a2 = P2[3*c+2];
        float2 b0 = G2[3*c], b1 = G2[3*c+1], b2 = G2[3*c+2];
        {
            float ax = a0.x - max_, ay = a0.y - may_, az = a1.x - maz_;
            float bx = b0.x - mbx,  by = b0.y - mby,  bz = b1.x - mbz;
            float ex = scale * (R00*ax + R01*ay + R02*az) - bx;
            float ey = scale * (R10*ax + R11*ay + R12*az) - by;
            float ez = scale * (R20*ax + R21*ay + R22*az) - bz;
            acc += sqrtf(ex*ex + ey*ey + ez*ez);
        }
        {
            float ax = a1.y - max_, ay = a2.x - may_, az = a2.y - maz_;
            float bx = b1.y - mbx,  by = b2.x - mby,  bz = b2.y - mbz;
            float ex = scale * (R00*ax + R01*ay + R02*az) - bx;
            float ey = scale * (R10*ax + R11*ay + R12*az) - by;
            float ez = scale * (R20*ax + R21*ay + R22*az) - bz;
            acc += sqrtf(ex*ex + ey*ey + ez*ez);
        }
    }
    out[elem] = acc * invJ;
}

extern "C" void kernel_launch(void* const* d_in, const int* in_sizes, int n_in,
                              void* d_out, int out_size)
{
    const float* pred = (const float*)d_in[0];
    const float* gt   = (const float*)d_in[1];
    float* out = (float*)d_out;
    const int B = out_size;
    const int blocks = (B + TPB - 1) / TPB;
    pampjpe_kernel<<<blocks, TPB>>>(pred, gt, out, B);
}

// round 5
// speedup vs baseline: 2.6022x; 1.9513x over previous
#include <cuda_runtime.h>
#include <math.h>

// PA-MPJPE via Horn quaternion + QUEST-style Newton eigenvalue + adjugate
// eigenvector. Pelvis alignment provably cancels (optimal translation).
// Per-warp staging: no block-wide barrier; MUFU fast paths on serial chains.

constexpr int J    = 14;
constexpr int FPE  = J * 3;          // 42 floats per element
constexpr int TPB  = 128;
constexpr int WELE = 32;             // elements per warp
constexpr int WF   = WELE * FPE;     // 1344 floats per warp per array
constexpr int WV4  = WF / 4;         // 336 float4

__device__ __forceinline__ float det3(float a, float b, float c,
                                      float d, float e, float f,
                                      float g, float h, float i) {
    return a * (e * i - f * h) - b * (d * i - f * g) + c * (d * h - e * g);
}

__global__ void __launch_bounds__(TPB, 5)
pampjpe_kernel(const float* __restrict__ pred,
               const float* __restrict__ gt,
               float* __restrict__ out, int B)
{
    __shared__ float sp[TPB * FPE];
    __shared__ float sg[TPB * FPE];
    const int tid  = threadIdx.x;
    const int warp = tid >> 5;
    const int lane = tid & 31;

    const long long elem0 = (long long)blockIdx.x * TPB + warp * WELE;
    const long long fbase = elem0 * FPE;
    const long long total = (long long)B * FPE;

    float* swp = sp + warp * WF;
    float* swg = sg + warp * WF;

    // ---- per-warp staging: global -> shared, fully coalesced ----
    if (fbase + WF <= total) {
        const float4* pin = reinterpret_cast<const float4*>(pred + fbase);
        const float4* gin = reinterpret_cast<const float4*>(gt   + fbase);
        float4* sp4 = reinterpret_cast<float4*>(swp);
        float4* sg4 = reinterpret_cast<float4*>(swg);
        // issue all loads first (deep MLP), then stores
        float4 rp[11], rg[11];
        #pragma unroll
        for (int i = 0; i < 10; i++) { rp[i] = pin[lane + 32*i]; rg[i] = gin[lane + 32*i]; }
        if (lane < 16) { rp[10] = pin[lane + 320]; rg[10] = gin[lane + 320]; }
        #pragma unroll
        for (int i = 0; i < 10; i++) { sp4[lane + 32*i] = rp[i]; sg4[lane + 32*i] = rg[i]; }
        if (lane < 16) { sp4[lane + 320] = rp[10]; sg4[lane + 320] = rg[10]; }
    } else if (fbase < total) {
        int rem = (int)(total - fbase);
        for (int idx = lane; idx < rem; idx += 32) {
            swp[idx] = pred[fbase + idx];
            swg[idx] = gt[fbase + idx];
        }
    }
    __syncwarp();

    const long long elem = elem0 + lane;
    if (elem >= B) return;

    const float2* P2 = reinterpret_cast<const float2*>(swp + lane * FPE);
    const float2* G2 = reinterpret_cast<const float2*>(swg + lane * FPE);

    // ---- pass 1: sums, |a|^2, cross-covariance S = sum a b^T ----
    float sax = 0.f, say = 0.f, saz = 0.f;
    float sbx = 0.f, sby = 0.f, sbz = 0.f;
    float saa = 0.f;
    float S00 = 0.f, S01 = 0.f, S02 = 0.f;
    float S10 = 0.f, S11 = 0.f, S12 = 0.f;
    float S20 = 0.f, S21 = 0.f, S22 = 0.f;
    #pragma unroll
    for (int c = 0; c < 7; c++) {
        float2 a0 = P2[3*c], a1 = P2[3*c+1], a2 = P2[3*c+2];
        float2 b0 = G2[3*c], b1 = G2[3*c+1], b2 = G2[3*c+2];
        {
            float ax = a0.x, ay = a0.y, az = a1.x;
            float bx = b0.x, by = b0.y, bz = b1.x;
            sax += ax; say += ay; saz += az;
            sbx += bx; sby += by; sbz += bz;
            saa += ax*ax + ay*ay + az*az;
            S00 += ax*bx; S01 += ax*by; S02 += ax*bz;
            S10 += ay*bx; S11 += ay*by; S12 += ay*bz;
            S20 += az*bx; S21 += az*by; S22 += az*bz;
        }
        {
            float ax = a1.y, ay = a2.x, az = a2.y;
            float bx = b1.y, by = b2.x, bz = b2.y;
            sax += ax; say += ay; saz += az;
            sbx += bx; sby += by; sbz += bz;
            saa += ax*ax + ay*ay + az*az;
            S00 += ax*bx; S01 += ax*by; S02 += ax*bz;
            S10 += ay*bx; S11 += ay*by; S12 += ay*bz;
            S20 += az*bx; S21 += az*by; S22 += az*bz;
        }
    }
    const float invJ = 1.0f / (float)J;
    const float max_ = sax*invJ, may_ = say*invJ, maz_ = saz*invJ;
    const float mbx  = sbx*invJ, mby  = sby*invJ, mbz  = sbz*invJ;

    // centered covariance K and var1
    const float K00 = S00 - sax*mbx, K01 = S01 - sax*mby, K02 = S02 - sax*mbz;
    const float K10 = S10 - say*mbx, K11 = S11 - say*mby, K12 = S12 - say*mbz;
    const float K20 = S20 - saz*mbx, K21 = S21 - saz*mby, K22 = S22 - saz*mbz;
    const float var1 = saa - (sax*max_ + say*may_ + saz*maz_);

    // ---- Horn's symmetric traceless 4x4 N ----
    const float n00 =  K00 + K11 + K22;
    const float n01 =  K12 - K21;
    const float n02 =  K20 - K02;
    const float n03 =  K01 - K10;
    const float n11 =  K00 - K11 - K22;
    const float n12 =  K01 + K10;
    const float n13 =  K20 + K02;
    const float n22 = -K00 + K11 - K22;
    const float n23 =  K12 + K21;
    const float n33 = -K00 - K11 + K22;

    // ---- characteristic quartic via power traces (trace N = 0) ----
    const float t00 = n00*n00 + n01*n01 + n02*n02 + n03*n03;
    const float t01 = n00*n01 + n01*n11 + n02*n12 + n03*n13;
    const float t02 = n00*n02 + n01*n12 + n02*n22 + n03*n23;
    const float t03 = n00*n03 + n01*n13 + n02*n23 + n03*n33;
    const float t11 = n01*n01 + n11*n11 + n12*n12 + n13*n13;
    const float t12 = n01*n02 + n11*n12 + n12*n22 + n13*n23;
    const float t13 = n01*n03 + n11*n13 + n12*n23 + n13*n33;
    const float t22 = n02*n02 + n12*n12 + n22*n22 + n23*n23;
    const float t23 = n02*n03 + n12*n13 + n22*n23 + n23*n33;
    const float t33 = n03*n03 + n13*n13 + n23*n23 + n33*n33;

    const float p2 = t00 + t11 + t22 + t33;
    const float p3 = n00*t00 + n11*t11 + n22*t22 + n33*t33
                   + 2.f*(n01*t01 + n02*t02 + n03*t03
                        + n12*t12 + n13*t13 + n23*t23);
    const float p4 = t00*t00 + t11*t11 + t22*t22 + t33*t33
                   + 2.f*(t01*t01 + t02*t02 + t03*t03
                        + t12*t12 + t13*t13 + t23*t23);

    // char poly: l^4 + c2 l^2 + c1 l + c0
    const float c2 = -0.5f * p2;
    const float c1 = -(1.0f/3.0f) * p3;
    const float c0 = 0.125f * p2 * p2 - 0.25f * p4;

    // Newton from upper bound sqrt(3/4 * p2) >= lambda_max (monotone)
    float lam = 0.75f * p2;
    lam = lam * rsqrtf(fmaxf(lam, 1e-30f));     // sqrt via MUFU
    #pragma unroll
    for (int it = 0; it < 6; it++) {
        float lam2 = lam * lam;
        float f  = ((lam2 + c2) * lam + c1) * lam + c0;
        float fp = (4.f * lam2 + 2.f * c2) * lam + c1;
        lam -= __fdividef(f, fmaxf(fp, 1e-20f));
    }

    // ---- eigenvector = column of adj(N - lam I) (pick best-conditioned) ----
    const float m00 = n00 - lam, m11 = n11 - lam;
    const float m22 = n22 - lam, m33 = n33 - lam;

    const float a00 =  det3(m11, n12, n13,  n12, m22, n23,  n13, n23, m33);
    const float a01 = -det3(n01, n12, n13,  n02, m22, n23,  n03, n23, m33);
    const float a02 =  det3(n01, m11, n13,  n02, n12, n23,  n03, n13, m33);
    const float a03 = -det3(n01, m11, n12,  n02, n12, m22,  n03, n13, n23);
    const float a11 =  det3(m00, n02, n03,  n02, m22, n23,  n03, n23, m33);
    const float a12 = -det3(m00, n01, n03,  n02, n12, n23,  n03, n13, m33);
    const float a13 =  det3(m00, n01, n02,  n02, n12, m22,  n03, n13, n23);
    const float a22 =  det3(m00, n01, n03,  n01, m11, n13,  n03, n13, m33);
    const float a23 = -det3(m00, n01, n02,  n01, m11, n12,  n03, n13, n23);
    const float a33 =  det3(m00, n01, n02,  n01, m11, n12,  n02, n12, m22);

    float best = fabsf(a00);
    float qw = a00, qx = a01, qy = a02, qz = a03;
    if (fabsf(a11) > best) { best = fabsf(a11); qw = a01; qx = a11; qy = a12; qz = a13; }
    if (fabsf(a22) > best) { best = fabsf(a22); qw = a02; qx = a12; qy = a22; qz = a23; }
    if (fabsf(a33) > best) { best = fabsf(a33); qw = a03; qx = a13; qy = a23; qz = a33; }

    const float rn = rsqrtf(qw*qw + qx*qx + qy*qy + qz*qz);
    qw *= rn; qx *= rn; qy *= rn; qz *= rn;

    // quaternion -> rotation
    const float xx = qx*qx, yy = qy*qy, zz = qz*qz;
    const float xy = qx*qy, xz = qx*qz, yz = qy*qz;
    const float wx = qw*qx, wy = qw*qy, wz = qw*qz;
    const float R00 = 1.f - 2.f*(yy + zz), R01 = 2.f*(xy - wz),       R02 = 2.f*(xz + wy);
    const float R10 = 2.f*(xy + wz),       R11 = 1.f - 2.f*(xx + zz), R12 = 2.f*(yz - wx);
    const float R20 = 2.f*(xz - wy),       R21 = 2.f*(yz + wx),       R22 = 1.f - 2.f*(xx + yy);

    // scale = trace(R K)/var1 (explicit, robust to Newton residual)
    const float trRK = R00*K00 + R01*K10 + R02*K20
                     + R10*K01 + R11*K11 + R12*K21
                     + R20*K02 + R21*K12 + R22*K22;
    const float scale = __fdividef(trRK, var1);

    // ---- pass 2: loss = mean_j || scale*R*(a_j - mu_a) - (b_j - mu_b) || ----
    float acc = 0.f;
    #pragma unroll
    for (int c = 0; c < 7; c++) {
        float2 a0 = P2[3*c], a1 = P2[3*c+1], a2 = P2[3*c+2];
        float2 b0 = G2[3*c], b1 = G2[3*c+1], b2 = G2[3*c+2];
        {
            float ax = a0.x - max_, ay = a0.y - may_, az = a1.x - maz_;
            float bx = b0.x - mbx,  by = b0.y - mby,  bz = b1.x - mbz;
            float ex = scale * (R00*ax + R01*ay + R02*az) - bx;
            float ey = scale * (R10*ax + R11*ay + R12*az) - by;
            float ez = scale * (R20*ax + R21*ay + R22*az) - bz;
            float d2 = ex*ex + ey*ey + ez*ez;
            acc += d2 * rsqrtf(fmaxf(d2, 1e-24f));   // sqrt via MUFU.RSQ
        }
        {
            float ax = a1.y - max_, ay = a2.x - may_, az = a2.y - maz_;
            float bx = b1.y - mbx,  by = b2.x - mby,  bz = b2.y - mbz;
            float ex = scale * (R00*ax + R01*ay + R02*az) - bx;
            float ey = scale * (R10*ax + R11*ay + R12*az) - by;
            float ez = scale * (R20*ax + R21*ay + R22*az) - bz;
            float d2 = ex*ex + ey*ey + ez*ez;
            acc += d2 * rsqrtf(fmaxf(d2, 1e-24f));
        }
    }
    out[elem] = acc * invJ;
}

extern "C" void kernel_launch(void* const* d_in, const int* in_sizes, int n_in,
                              void* d_out, int out_size)
{
    const float* pred = (const float*)d_in[0];
    const float* gt   = (const float*)d_in[1];
    float* out = (float*)d_out;
    const int B = out_size;
    const int blocks = (B + TPB - 1) / TPB;
    pampjpe_kernel<<<blocks, TPB>>>(pred, gt, out, B);
}

// round 6
// speedup vs baseline: 3.4972x; 1.3439x over previous
#include <cuda_runtime.h>
#include <math.h>
#include <stdint.h>

// PA-MPJPE: Horn quaternion + QUEST Newton eigenvalue + adjugate eigenvector.
// Persistent CTAs, per-warp double-buffered cp.async pipeline (DRAM latency
// hidden behind previous tile's compute). Pelvis alignment provably cancels.

constexpr int J     = 14;
constexpr int FPE   = J * 3;               // 42 floats per element
constexpr int EPW   = 32;                  // elements per warp
constexpr int WARPS = 4;
constexpr int TPB   = WARPS * 32;          // 128
constexpr int EPT   = WARPS * EPW;         // 128 elements per CTA-tile
constexpr int WB_ARR = EPW * FPE * 4;      // 5376 B per array per warp
constexpr int WBYTES = 2 * WB_ARR;         // 10752 B per warp (pred+gt)
constexpr int TILE_BYTES = WARPS * WBYTES; // 43008 B
constexpr int SMEM_BYTES = 2 * TILE_BYTES; // 86016 B (double buffer)
constexpr int GRID  = 304;                 // 2 CTAs/SM x 152 SMs (GB300)

__device__ __forceinline__ uint32_t smem_u32(const void* p) {
    uint32_t a;
    asm("{ .reg .u64 t; cvta.to.shared.u64 t, %1; cvt.u32.u64 %0, t; }"
        : "=r"(a) : "l"(p));
    return a;
}

__device__ __forceinline__ void cp16(uint32_t s, const void* g) {
    asm volatile("cp.async.cg.shared.global [%0], [%1], 16;"
                 :: "r"(s), "l"(g) : "memory");
}
__device__ __forceinline__ void cp4(uint32_t s, const void* g) {
    asm volatile("cp.async.ca.shared.global [%0], [%1], 4;"
                 :: "r"(s), "l"(g) : "memory");
}
__device__ __forceinline__ void cp_commit() {
    asm volatile("cp.async.commit_group;" ::: "memory");
}
template<int N>
__device__ __forceinline__ void cp_wait() {
    asm volatile("cp.async.wait_group %0;" :: "n"(N) : "memory");
}

__device__ __forceinline__ float det3(float a, float b, float c,
                                      float d, float e, float f,
                                      float g, float h, float i) {
    return a * (e * i - f * h) - b * (d * i - f * g) + c * (d * h - e * g);
}

// Prefetch this warp's 32-element slice of a tile into its shared region.
__device__ __forceinline__ void prefetch_slice(uint32_t sbase,
                                               const float* __restrict__ pred,
                                               const float* __restrict__ gt,
                                               long long fbase, long long total,
                                               int lane)
{
    if (fbase + EPW * FPE <= total) {
        const char* gp = (const char*)(pred + fbase);
        const char* gg = (const char*)(gt   + fbase);
        #pragma unroll
        for (int i = 0; i < 10; i++) {
            int o = (lane + 32 * i) * 16;
            cp16(sbase + o,          gp + o);
            cp16(sbase + WB_ARR + o, gg + o);
        }
        if (lane < 16) {
            int o = (320 + lane) * 16;
            cp16(sbase + o,          gp + o);
            cp16(sbase + WB_ARR + o, gg + o);
        }
    } else if (fbase < total) {
        int rem = (int)(total - fbase);
        for (int idx = lane; idx < rem; idx += 32) {
            cp4(sbase + idx * 4,          (const void*)(pred + fbase + idx));
            cp4(sbase + WB_ARR + idx * 4, (const void*)(gt   + fbase + idx));
        }
    }
}

__device__ __forceinline__ float compute_elem(const float* __restrict__ pw,
                                              const float* __restrict__ gw,
                                              int lane)
{
    const float2* P2 = reinterpret_cast<const float2*>(pw + lane * FPE);
    const float2* G2 = reinterpret_cast<const float2*>(gw + lane * FPE);

    // ---- pass 1: sums, |a|^2, cross-covariance S = sum a b^T ----
    float sax = 0.f, say = 0.f, saz = 0.f;
    float sbx = 0.f, sby = 0.f, sbz = 0.f;
    float saa = 0.f;
    float S00 = 0.f, S01 = 0.f, S02 = 0.f;
    float S10 = 0.f, S11 = 0.f, S12 = 0.f;
    float S20 = 0.f, S21 = 0.f, S22 = 0.f;
    #pragma unroll
    for (int c = 0; c < 7; c++) {
        float2 a0 = P2[3*c], a1 = P2[3*c+1], a2 = P2[3*c+2];
        float2 b0 = G2[3*c], b1 = G2[3*c+1], b2 = G2[3*c+2];
        {
            float ax = a0.x, ay = a0.y, az = a1.x;
            float bx = b0.x, by = b0.y, bz = b1.x;
            sax += ax; say += ay; saz += az;
            sbx += bx; sby += by; sbz += bz;
            saa += ax*ax + ay*ay + az*az;
            S00 += ax*bx; S01 += ax*by; S02 += ax*bz;
            S10 += ay*bx; S11 += ay*by; S12 += ay*bz;
            S20 += az*bx; S21 += az*by; S22 += az*bz;
        }
        {
            float ax = a1.y, ay = a2.x, az = a2.y;
            float bx = b1.y, by = b2.x, bz = b2.y;
            sax += ax; say += ay; saz += az;
            sbx += bx; sby += by; sbz += bz;
            saa += ax*ax + ay*ay + az*az;
            S00 += ax*bx; S01 += ax*by; S02 += ax*bz;
            S10 += ay*bx; S11 += ay*by; S12 += ay*bz;
            S20 += az*bx; S21 += az*by; S22 += az*bz;
        }
    }
    const float invJ = 1.0f / (float)J;
    const float max_ = sax*invJ, may_ = say*invJ, maz_ = saz*invJ;
    const float mbx  = sbx*invJ, mby  = sby*invJ, mbz  = sbz*invJ;

    const float K00 = S00 - sax*mbx, K01 = S01 - sax*mby, K02 = S02 - sax*mbz;
    const float K10 = S10 - say*mbx, K11 = S11 - say*mby, K12 = S12 - say*mbz;
    const float K20 = S20 - saz*mbx, K21 = S21 - saz*mby, K22 = S22 - saz*mbz;
    const float var1 = saa - (sax*max_ + say*may_ + saz*maz_);

    // ---- Horn's symmetric traceless 4x4 N ----
    const float n00 =  K00 + K11 + K22;
    const float n01 =  K12 - K21;
    const float n02 =  K20 - K02;
    const float n03 =  K01 - K10;
    const float n11 =  K00 - K11 - K22;
    const float n12 =  K01 + K10;
    const float n13 =  K20 + K02;
    const float n22 = -K00 + K11 - K22;
    const float n23 =  K12 + K21;
    const float n33 = -K00 - K11 + K22;

    // ---- characteristic quartic via power traces ----
    const float t00 = n00*n00 + n01*n01 + n02*n02 + n03*n03;
    const float t01 = n00*n01 + n01*n11 + n02*n12 + n03*n13;
    const float t02 = n00*n02 + n01*n12 + n02*n22 + n03*n23;
    const float t03 = n00*n03 + n01*n13 + n02*n23 + n03*n33;
    const float t11 = n01*n01 + n11*n11 + n12*n12 + n13*n13;
    const float t12 = n01*n02 + n11*n12 + n12*n22 + n13*n23;
    const float t13 = n01*n03 + n11*n13 + n12*n23 + n13*n33;
    const float t22 = n02*n02 + n12*n12 + n22*n22 + n23*n23;
    const float t23 = n02*n03 + n12*n13 + n22*n23 + n23*n33;
    const float t33 = n03*n03 + n13*n13 + n23*n23 + n33*n33;

    const float p2 = t00 + t11 + t22 + t33;
    const float p3 = n00*t00 + n11*t11 + n22*t22 + n33*t33
                   + 2.f*(n01*t01 + n02*t02 + n03*t03
                        + n12*t12 + n13*t13 + n23*t23);
    const float p4 = t00*t00 + t11*t11 + t22*t22 + t33*t33
                   + 2.f*(t01*t01 + t02*t02 + t03*t03
                        + t12*t12 + t13*t13 + t23*t23);

    const float c2 = -0.5f * p2;
    const float c1 = -(1.0f/3.0f) * p3;
    const float c0 = 0.125f * p2 * p2 - 0.25f * p4;

    float lam = 0.75f * p2;
    lam = lam * rsqrtf(fmaxf(lam, 1e-30f));
    #pragma unroll
    for (int it = 0; it < 6; it++) {
        float lam2 = lam * lam;
        float f  = ((lam2 + c2) * lam + c1) * lam + c0;
        float fp = (4.f * lam2 + 2.f * c2) * lam + c1;
        lam -= __fdividef(f, fmaxf(fp, 1e-20f));
    }

    // ---- eigenvector = best column of adj(N - lam I) ----
    const float m00 = n00 - lam, m11 = n11 - lam;
    const float m22 = n22 - lam, m33 = n33 - lam;

    const float a00 =  det3(m11, n12, n13,  n12, m22, n23,  n13, n23, m33);
    const float a01 = -det3(n01, n12, n13,  n02, m22, n23,  n03, n23, m33);
    const float a02 =  det3(n01, m11, n13,  n02, n12, n23,  n03, n13, m33);
    const float a03 = -det3(n01, m11, n12,  n02, n12, m22,  n03, n13, n23);
    const float a11 =  det3(m00, n02, n03,  n02, m22, n23,  n03, n23, m33);
    const float a12 = -det3(m00, n01, n03,  n02, n12, n23,  n03, n13, m33);
    const float a13 =  det3(m00, n01, n02,  n02, n12, m22,  n03, n13, n23);
    const float a22 =  det3(m00, n01, n03,  n01, m11, n13,  n03, n13, m33);
    const float a23 = -det3(m00, n01, n02,  n01, m11, n12,  n03, n13, n23);
    const float a33 =  det3(m00, n01, n02,  n01, m11, n12,  n02, n12, m22);

    float best = fabsf(a00);
    float qw = a00, qx = a01, qy = a02, qz = a03;
    if (fabsf(a11) > best) { best = fabsf(a11); qw = a01; qx = a11; qy = a12; qz = a13; }
    if (fabsf(a22) > best) { best = fabsf(a22); qw = a02; qx = a12; qy = a22; qz = a23; }
    if (fabsf(a33) > best) { best = fabsf(a33); qw = a03; qx = a13; qy = a23; qz = a33; }

    const float rn = rsqrtf(qw*qw + qx*qx + qy*qy + qz*qz);
    qw *= rn; qx *= rn; qy *= rn; qz *= rn;

    const float xx = qx*qx, yy = qy*qy, zz = qz*qz;
    const float xy = qx*qy, xz = qx*qz, yz = qy*qz;
    const float wx = qw*qx, wy = qw*qy, wz = qw*qz;
    const float R00 = 1.f - 2.f*(yy + zz), R01 = 2.f*(xy - wz),       R02 = 2.f*(xz + wy);
    const float R10 = 2.f*(xy + wz),       R11 = 1.f - 2.f*(xx + zz), R12 = 2.f*(yz - wx);
    const float R20 = 2.f*(xz - wy),       R21 = 2.f*(yz + wx),       R22 = 1.f - 2.f*(xx + yy);

    const float trRK = R00*K00 + R01*K10 + R02*K20
                     + R10*K01 + R11*K11 + R12*K21
                     + R20*K02 + R21*K12 + R22*K22;
    const float s = __fdividef(trRK, var1);

    // fold: r_j = (M a_j + c) - b_j,  M = s R,  c = mu_b - M mu_a
    const float M00 = s*R00, M01 = s*R01, M02 = s*R02;
    const float M10 = s*R10, M11 = s*R11, M12 = s*R12;
    const float M20 = s*R20, M21 = s*R21, M22 = s*R22;
    const float cx = mbx - (M00*max_ + M01*may_ + M02*maz_);
    const float cy = mby - (M10*max_ + M11*may_ + M12*maz_);
    const float cz = mbz - (M20*max_ + M21*may_ + M22*maz_);

    float acc = 0.f;
    #pragma unroll
    for (int c = 0; c < 7; c++) {
        float2 a0 = P2[3*c], a1 = P2[3*c+1], a2 = P2[3*c+2];
        float2 b0 = G2[3*c], b1 = G2[3*c+1], b2 = G2[3*c+2];
        {
            float ax = a0.x, ay = a0.y, az = a1.x;
            float ex = (M00*ax + M01*ay + M02*az + cx) - b0.x;
            float ey = (M10*ax + M11*ay + M12*az + cy) - b0.y;
            float ez = (M20*ax + M21*ay + M22*az + cz) - b1.x;
            float d2 = ex*ex + ey*ey + ez*ez;
            acc += d2 * rsqrtf(fmaxf(d2, 1e-24f));
        }
        {
            float ax = a1.y, ay = a2.x, az = a2.y;
            float ex = (M00*ax + M01*ay + M02*az + cx) - b1.y;
            float ey = (M10*ax + M11*ay + M12*az + cy) - b2.x;
            float ez = (M20*ax + M21*ay + M22*az + cz) - b2.y;
            float d2 = ex*ex + ey*ey + ez*ez;
            acc += d2 * rsqrtf(fmaxf(d2, 1e-24f));
        }
    }
    return acc * invJ;
}

__global__ void __launch_bounds__(TPB, 2)
pampjpe_kernel(const float* __restrict__ pred,
               const float* __restrict__ gt,
               float* __restrict__ out, int B)
{
    extern __shared__ float smem[];
    const int tid  = threadIdx.x;
    const int warp = tid >> 5;
    const int lane = tid & 31;
    const long long total = (long long)B * FPE;
    const int ntiles = (B + EPT - 1) / EPT;

    // this warp's region in each of the two buffers
    const uint32_t w0 = smem_u32(smem) + warp * WBYTES;
    const uint32_t wreg[2] = { w0, w0 + (uint32_t)TILE_BYTES };
    const float* wptr[2] = {
        smem + (warp * WBYTES) / 4,
        smem + (TILE_BYTES + warp * WBYTES) / 4
    };

    int tile = blockIdx.x;
    if (tile >= ntiles) return;

    // prime the pipeline
    {
        long long fbase = ((long long)tile * EPT + warp * EPW) * FPE;
        prefetch_slice(wreg[0], pred, gt, fbase, total, lane);
        cp_commit();
    }

    int buf = 0;
    for (; tile < ntiles; tile += GRID) {
        int next = tile + GRID;
        if (next < ntiles) {
            long long fn = ((long long)next * EPT + warp * EPW) * FPE;
            prefetch_slice(wreg[buf ^ 1], pred, gt, fn, total, lane);
            cp_commit();
            cp_wait<1>();
        } else {
            cp_wait<0>();
        }
        __syncwarp();

        long long elem = (long long)tile * EPT + warp * EPW + lane;
        if (elem < B) {
            const float* pw = wptr[buf];
            const float* gw = pw + WB_ARR / 4;
            out[elem] = compute_elem(pw, gw, lane);
        }
        __syncwarp();   // all lanes done reading before next overwrite
        buf ^= 1;
    }
}

extern "C" void kernel_launch(void* const* d_in, const int* in_sizes, int n_in,
                              void* d_out, int out_size)
{
    const float* pred = (const float*)d_in[0];
    const float* gt   = (const float*)d_in[1];
    float* out = (float*)d_out;
    const int B = out_size;
    const int ntiles = (B + EPT - 1) / EPT;
    const int grid = GRID < ntiles ? GRID : ntiles;

    static bool attr_set = false;
    if (!attr_set) {
        cudaFuncSetAttribute(pampjpe_kernel,
                             cudaFuncAttributeMaxDynamicSharedMemorySize,
                             SMEM_BYTES);
        attr_set = true;
    }
    pampjpe_kernel<<<grid, TPB, SMEM_BYTES>>>(pred, gt, out, B);
}

// round 8
// speedup vs baseline: 3.5503x; 1.0152x over previous
#include <cuda_runtime.h>
#include <math.h>
#include <stdint.h>

// PA-MPJPE: Horn quaternion + QUEST Newton eigenvalue + adjugate eigenvector.
// Persistent CTAs, per-warp double-buffered cp.async pipeline.
// R7: EPW 32->28 shrinks smem/warp to 18.4KB -> 3 CTAs/SM (12 warps/SM),
// attacking the SMSP issue bound (52.7% at 2 warps/SMSP).

constexpr int J     = 14;
constexpr int FPE   = J * 3;               // 42 floats per element
constexpr int EPW   = 28;                  // elements per warp (4 lanes idle in compute)
constexpr int WARPS = 4;
constexpr int TPB   = WARPS * 32;          // 128
constexpr int EPT   = WARPS * EPW;         // 112 elements per CTA-tile
constexpr int WB_ARR = EPW * FPE * 4;      // 4704 B per array per warp
constexpr int WV4_FULL = (WB_ARR / 16);    // 294 float4 per array per warp
constexpr int WBYTES = 2 * WB_ARR;         // 9408 B per warp (pred+gt)
constexpr int TILE_BYTES = WARPS * WBYTES; // 37632 B
constexpr int SMEM_BYTES = 2 * TILE_BYTES; // 75264 B (double buffer)
constexpr int GRID  = 456;                 // 3 CTAs/SM x 152 SMs (GB300)

__device__ __forceinline__ uint32_t smem_u32(const void* p) {
    uint32_t a;
    asm("{ .reg .u64 t; cvta.to.shared.u64 t, %1; cvt.u32.u64 %0, t; }"
        : "=r"(a) : "l"(p));
    return a;
}

__device__ __forceinline__ void cp16(uint32_t s, const void* g) {
    asm volatile("cp.async.cg.shared.global [%0], [%1], 16;"
                 :: "r"(s), "l"(g) : "memory");
}
__device__ __forceinline__ void cp4(uint32_t s, const void* g) {
    asm volatile("cp.async.ca.shared.global [%0], [%1], 4;"
                 :: "r"(s), "l"(g) : "memory");
}
__device__ __forceinline__ void cp_commit() {
    asm volatile("cp.async.commit_group;" ::: "memory");
}
template<int N>
__device__ __forceinline__ void cp_wait() {
    asm volatile("cp.async.wait_group %0;" :: "n"(N) : "memory");
}

__device__ __forceinline__ float det3(float a, float b, float c,
                                      float d, float e, float f,
                                      float g, float h, float i) {
    return a * (e * i - f * h) - b * (d * i - f * g) + c * (d * h - e * g);
}

// Prefetch this warp's EPW-element slice of a tile into its shared region.
__device__ __forceinline__ void prefetch_slice(uint32_t sbase,
                                               const float* __restrict__ pred,
                                               const float* __restrict__ gt,
                                               long long fbase, long long total,
                                               int lane)
{
    if (fbase + EPW * FPE <= total) {
        const char* gp = (const char*)(pred + fbase);
        const char* gg = (const char*)(gt   + fbase);
        #pragma unroll
        for (int i = 0; i < 9; i++) {          // 9*32 = 288 float4
            int o = (lane + 32 * i) * 16;
            cp16(sbase + o,          gp + o);
            cp16(sbase + WB_ARR + o, gg + o);
        }
        if (lane < WV4_FULL - 288) {           // tail: 6 float4
            int o = (288 + lane) * 16;
            cp16(sbase + o,          gp + o);
            cp16(sbase + WB_ARR + o, gg + o);
        }
    } else if (fbase < total) {
        int rem = (int)(total - fbase);
        for (int idx = lane; idx < rem; idx += 32) {
            cp4(sbase + idx * 4,          (const void*)(pred + fbase + idx));
            cp4(sbase + WB_ARR + idx * 4, (const void*)(gt   + fbase + idx));
        }
    }
}

__device__ __forceinline__ float compute_elem(const float* __restrict__ pw,
                                              const float* __restrict__ gw,
                                              int lane)
{
    const float2* P2 = reinterpret_cast<const float2*>(pw + lane * FPE);
    const float2* G2 = reinterpret_cast<const float2*>(gw + lane * FPE);

    // ---- pass 1: sums, |a|^2, cross-covariance S = sum a b^T ----
    float sax = 0.f, say = 0.f, saz = 0.f;
    float sbx = 0.f, sby = 0.f, sbz = 0.f;
    float saa = 0.f;
    float S00 = 0.f, S01 = 0.f, S02 = 0.f;
    float S10 = 0.f, S11 = 0.f, S12 = 0.f;
    float S20 = 0.f, S21 = 0.f, S22 = 0.f;
    #pragma unroll
    for (int c = 0; c < 7; c++) {
        float2 a0 = P2[3*c], a1 = P2[3*c+1], a2 = P2[3*c+2];
        float2 b0 = G2[3*c], b1 = G2[3*c+1], b2 = G2[3*c+2];
        {
            float ax = a0.x, ay = a0.y, az = a1.x;
            float bx = b0.x, by = b0.y, bz = b1.x;
            sax += ax; say += ay; saz += az;
            sbx += bx; sby += by; sbz += bz;
            saa += ax*ax + ay*ay + az*az;
            S00 += ax*bx; S01 += ax*by; S02 += ax*bz;
            S10 += ay*bx; S11 += ay*by; S12 += ay*bz;
            S20 += az*bx; S21 += az*by; S22 += az*bz;
        }
        {
            float ax = a1.y, ay = a2.x, az = a2.y;
            float bx = b1.y, by = b2.x, bz = b2.y;
            sax += ax; say += ay; saz += az;
            sbx += bx; sby += by; sbz += bz;
            saa += ax*ax + ay*ay + az*az;
            S00 += ax*bx; S01 += ax*by; S02 += ax*bz;
            S10 += ay*bx; S11 += ay*by; S12 += ay*bz;
            S20 += az*bx; S21 += az*by; S22 += az*bz;
        }
    }
    const float invJ = 1.0f / (float)J;
    const float max_ = sax*invJ, may_ = say*invJ, maz_ = saz*invJ;
    const float mbx  = sbx*invJ, mby  = sby*invJ, mbz  = sbz*invJ;

    const float K00 = S00 - sax*mbx, K01 = S01 - sax*mby, K02 = S02 - sax*mbz;
    const float K10 = S10 - say*mbx, K11 = S11 - say*mby, K12 = S12 - say*mbz;
    const float K20 = S20 - saz*mbx, K21 = S21 - saz*mby, K22 = S22 - saz*mbz;
    const float var1 = saa - (sax*max_ + say*may_ + saz*maz_);

    // ---- Horn's symmetric traceless 4x4 N ----
    const float n00 =  K00 + K11 + K22;
    const float n01 =  K12 - K21;
    const float n02 =  K20 - K02;
    const float n03 =  K01 - K10;
    const float n11 =  K00 - K11 - K22;
    const float n12 =  K01 + K10;
    const float n13 =  K20 + K02;
    const float n22 = -K00 + K11 - K22;
    const float n23 =  K12 + K21;
    const float n33 = -K00 - K11 + K22;

    // ---- characteristic quartic via power traces ----
    const float t00 = n00*n00 + n01*n01 + n02*n02 + n03*n03;
    const float t01 = n00*n01 + n01*n11 + n02*n12 + n03*n13;
    const float t02 = n00*n02 + n01*n12 + n02*n22 + n03*n23;
    const float t03 = n00*n03 + n01*n13 + n02*n23 + n03*n33;
    const float t11 = n01*n01 + n11*n11 + n12*n12 + n13*n13;
    const float t12 = n01*n02 + n11*n12 + n12*n22 + n13*n23;
    const float t13 = n01*n03 + n11*n13 + n12*n23 + n13*n33;
    const float t22 = n02*n02 + n12*n12 + n22*n22 + n23*n23;
    const float t23 = n02*n03 + n12*n13 + n22*n23 + n23*n33;
    const float t33 = n03*n03 + n13*n13 + n23*n23 + n33*n33;

    const float p2 = t00 + t11 + t22 + t33;
    const float p3 = n00*t00 + n11*t11 + n22*t22 + n33*t33
                   + 2.f*(n01*t01 + n02*t02 + n03*t03
                        + n12*t12 + n13*t13 + n23*t23);
    const float p4 = t00*t00 + t11*t11 + t22*t22 + t33*t33
                   + 2.f*(t01*t01 + t02*t02 + t03*t03
                        + t12*t12 + t13*t13 + t23*t23);

    const float c2 = -0.5f * p2;
    const float c1 = -(1.0f/3.0f) * p3;
    const float c0 = 0.125f * p2 * p2 - 0.25f * p4;

    float lam = 0.75f * p2;
    lam = lam * rsqrtf(fmaxf(lam, 1e-30f));
    #pragma unroll
    for (int it = 0; it < 6; it++) {
        float lam2 = lam * lam;
        float f  = ((lam2 + c2) * lam + c1) * lam + c0;
        float fp = (4.f * lam2 + 2.f * c2) * lam + c1;
        lam -= __fdividef(f, fmaxf(fp, 1e-20f));
    }

    // ---- eigenvector = best column of adj(N - lam I) ----
    const float m00 = n00 - lam, m11 = n11 - lam;
    const float m22 = n22 - lam, m33 = n33 - lam;

    const float a00 =  det3(m11, n12, n13,  n12, m22, n23,  n13, n23, m33);
    const float a01 = -det3(n01, n12, n13,  n02, m22, n23,  n03, n23, m33);
    const float a02 =  det3(n01, m11, n13,  n02, n12, n23,  n03, n13, m33);
    const float a03 = -det3(n01, m11, n12,  n02, n12, m22,  n03, n13, n23);
    const float a11 =  det3(m00, n02, n03,  n02, m22, n23,  n03, n23, m33);
    const float a12 = -det3(m00, n01, n03,  n02, n12, n23,  n03, n13, m33);
    const float a13 =  det3(m00, n01, n02,  n02, n12, m22,  n03, n13, n23);
    const float a22 =  det3(m00, n01, n03,  n01, m11, n13,  n03, n13, m33);
    const float a23 = -det3(m00, n01, n02,  n01, m11, n12,  n03, n13, n23);
    const float a33 =  det3(m00, n01, n02,  n01, m11, n12,  n02, n12, m22);

    float best = fabsf(a00);
    float qw = a00, qx = a01, qy = a02, qz = a03;
    if (fabsf(a11) > best) { best = fabsf(a11); qw = a01; qx = a11; qy = a12; qz = a13; }
    if (fabsf(a22) > best) { best = fabsf(a22); qw = a02; qx = a12; qy = a22; qz = a23; }
    if (fabsf(a33) > best) { best = fabsf(a33); qw = a03; qx = a13; qy = a23; qz = a33; }

    const float rn = rsqrtf(qw*qw + qx*qx + qy*qy + qz*qz);
    qw *= rn; qx *= rn; qy *= rn; qz *= rn;

    const float xx = qx*qx, yy = qy*qy, zz = qz*qz;
    const float xy = qx*qy, xz = qx*qz, yz = qy*qz;
    const float wx = qw*qx, wy = qw*qy, wz = qw*qz;
    const float R00 = 1.f - 2.f*(yy + zz), R01 = 2.f*(xy - wz),       R02 = 2.f*(xz + wy);
    const float R10 = 2.f*(xy + wz),       R11 = 1.f - 2.f*(xx + zz), R12 = 2.f*(yz - wx);
    const float R20 = 2.f*(xz - wy),       R21 = 2.f*(yz + wx),       R22 = 1.f - 2.f*(xx + yy);

    const float trRK = R00*K00 + R01*K10 + R02*K20
                     + R10*K01 + R11*K11 + R12*K21
                     + R20*K02 + R21*K12 + R22*K22;
    const float s = __fdividef(trRK, var1);

    // fold: r_j = (M a_j + c) - b_j,  M = s R,  c = mu_b - M mu_a
    const float M00 = s*R00, M01 = s*R01, M02 = s*R02;
    const float M10 = s*R10, M11 = s*R11, M12 = s*R12;
    const float M20 = s*R20, M21 = s*R21, M22 = s*R22;
    const float cx = mbx - (M00*max_ + M01*may_ + M02*maz_);
    const float cy = mby - (M10*max_ + M11*may_ + M12*maz_);
    const float cz = mbz - (M20*max_ + M21*may_ + M22*maz_);

    float acc = 0.f;
    #pragma unroll
    for (int c = 0; c < 7; c++) {
        float2 a0 = P2[3*c], a1 = P2[3*c+1], a2 = P2[3*c+2];
        float2 b0 = G2[3*c], b1 = G2[3*c+1], b2 = G2[3*c+2];
        {
            float ax = a0.x, ay = a0.y, az = a1.x;
            float ex = (M00*ax + M01*ay + M02*az + cx) - b0.x;
            float ey = (M10*ax + M11*ay + M12*az + cy) - b0.y;
            float ez = (M20*ax + M21*ay + M22*az + cz) - b1.x;
            float d2 = ex*ex + ey*ey + ez*ez;
            acc += d2 * rsqrtf(fmaxf(d2, 1e-24f));
        }
        {
            float ax = a1.y, ay = a2.x, az = a2.y;
            float ex = (M00*ax + M01*ay + M02*az + cx) - b1.y;
            float ey = (M10*ax + M11*ay + M12*az + cy) - b2.x;
            float ez = (M20*ax + M21*ay + M22*az + cz) - b2.y;
            float d2 = ex*ex + ey*ey + ez*ez;
            acc += d2 * rsqrtf(fmaxf(d2, 1e-24f));
        }
    }
    return acc * invJ;
}

__global__ void __launch_bounds__(TPB, 3)
pampjpe_kernel(const float* __restrict__ pred,
               const float* __restrict__ gt,
               float* __restrict__ out, int B)
{
    extern __shared__ float smem[];
    const int tid  = threadIdx.x;
    const int warp = tid >> 5;
    const int lane = tid & 31;
    const long long total = (long long)B * FPE;
    const int ntiles = (B + EPT - 1) / EPT;

    // this warp's region in each of the two buffers
    const uint32_t w0 = smem_u32(smem) + warp * WBYTES;
    const uint32_t wreg0 = w0;
    const uint32_t wreg1 = w0 + (uint32_t)TILE_BYTES;
    const float* wptr0 = smem + (warp * WBYTES) / 4;
    const float* wptr1 = smem + (TILE_BYTES + warp * WBYTES) / 4;

    int tile = blockIdx.x;
    if (tile >= ntiles) return;

    // prime the pipeline
    {
        long long fbase = ((long long)tile * EPT + warp * EPW) * FPE;
        prefetch_slice(wreg0, pred, gt, fbase, total, lane);
        cp_commit();
    }

    int buf = 0;
    for (; tile < ntiles; tile += GRID) {
        int next = tile + GRID;
        if (next < ntiles) {
            long long fn = ((long long)next * EPT + warp * EPW) * FPE;
            prefetch_slice(buf ? wreg0 : wreg1, pred, gt, fn, total, lane);
            cp_commit();
            cp_wait<1>();
        } else {
            cp_wait<0>();
        }
        __syncwarp();

        long long elem = (long long)tile * EPT + warp * EPW + lane;
        if (lane < EPW && elem < B) {
            const float* pw = buf ? wptr1 : wptr0;
            const float* gw = pw + WB_ARR / 4;
            out[elem] = compute_elem(pw, gw, lane);
        }
        __syncwarp();   // all lanes done reading before next overwrite
        buf ^= 1;
    }
}

extern "C" void kernel_launch(void* const* d_in, const int* in_sizes, int n_in,
                              void* d_out, int out_size)
{
    const float* pred = (const float*)d_in[0];
    const float* gt   = (const float*)d_in[1];
    float* out = (float*)d_out;
    const int B = out_size;
    const int ntiles = (B + EPT - 1) / EPT;
    const int grid = GRID < ntiles ? GRID : ntiles;

    static bool attr_set = false;
    if (!attr_set) {
        cudaFuncSetAttribute(pampjpe_kernel,
                             cudaFuncAttributeMaxDynamicSharedMemorySize,
                             SMEM_BYTES);
        attr_set = true;
    }
    pampjpe_kernel<<<grid, TPB, SMEM_BYTES>>>(pred, gt, out, B);
}